// round 4
// baseline (speedup 1.0000x reference)
#include <cuda_runtime.h>
#include <cstdint>

// ---------------------------------------------------------------------------
// Problem constants
// ---------------------------------------------------------------------------
#define NN    2048         // nodes / batch
#define CC    16           // channels of x
#define HH    32
#define WW    32
#define HW    (HH*WW)      // 1024
#define FEAT  (CC*HW)      // 16384 floats per node
#define EMAX  16384

// Scratch (device globals; no allocation allowed in kernel_launch)
__device__ float g_neigh   [NN * CC * HW];   // 134 MB
__device__ float g_nonneigh[NN * CC * HW];   // 134 MB
__device__ float g_h1      [NN * 32 * HW];   // 268 MB
__device__ float g_h2      [NN * 32 * HW];   // 268 MB
__device__ int   g_edges64;                  // 1 if edges buffer is int64
__device__ int   g_deg[NN];
__device__ int   g_off[NN + 1];
__device__ int   g_cur[NN];
__device__ int   g_adj[2 * EMAX];            // peer | (0x10000 if rel>0)

// ---------------------------------------------------------------------------
// Packed fp32x2 helpers (sm_100+: SASS FFMA2 — only reachable via PTX)
// ---------------------------------------------------------------------------
__device__ __forceinline__ unsigned long long pack2(float lo, float hi) {
    unsigned long long r;
    asm("mov.b64 %0, {%1, %2};" : "=l"(r) : "f"(lo), "f"(hi));
    return r;
}
__device__ __forceinline__ void unpack2(unsigned long long v, float& lo, float& hi) {
    asm("mov.b64 {%0, %1}, %2;" : "=f"(lo), "=f"(hi) : "l"(v));
}
__device__ __forceinline__ unsigned long long fma2(unsigned long long a,
                                                   unsigned long long b,
                                                   unsigned long long c) {
    unsigned long long d;
    asm("fma.rn.f32x2 %0, %1, %2, %3;" : "=l"(d) : "l"(a), "l"(b), "l"(c));
    return d;
}

// ---------------------------------------------------------------------------
// Edge decode (dtype decided at runtime by probe)
// ---------------------------------------------------------------------------
__device__ __forceinline__ void load_edge(const void* edges, int e,
                                          int& a, int& rel, int& b) {
    if (g_edges64) {
        const long long* p = (const long long*)edges;
        a = (int)p[3 * e + 0]; rel = (int)p[3 * e + 1]; b = (int)p[3 * e + 2];
    } else {
        const int* p = (const int*)edges;
        a = p[3 * e + 0]; rel = p[3 * e + 1]; b = p[3 * e + 2];
    }
}

__global__ void probe_dtype_kernel(const void* edges, int E) {
    const long long* e64 = (const long long*)edges;
    bool ok = true;
    int n = E < 8 ? E : 8;
    for (int i = 0; i < n; i++) {
        long long a   = e64[3 * i + 0];
        long long rel = e64[3 * i + 1];
        long long b   = e64[3 * i + 2];
        if (a < 0 || a >= NN || b < 0 || b >= NN ||
            !(rel == 1 || rel == -1)) { ok = false; break; }
    }
    g_edges64 = ok ? 1 : 0;
}

// ---------------------------------------------------------------------------
// CSR build
// ---------------------------------------------------------------------------
__global__ void csr_zero_kernel() {
    int i = blockIdx.x * blockDim.x + threadIdx.x;
    if (i < NN) g_deg[i] = 0;
}

__global__ void csr_count_kernel(const void* edges, int E) {
    int e = blockIdx.x * blockDim.x + threadIdx.x;
    if (e >= E) return;
    int a, rel, b;
    load_edge(edges, e, a, rel, b);
    if (a < 0 || a >= NN || b < 0 || b >= NN) return;
    atomicAdd(&g_deg[a], 1);
    atomicAdd(&g_deg[b], 1);
}

__global__ void __launch_bounds__(1024) csr_scan_kernel() {
    __shared__ int s[NN];
    int t = threadIdx.x;                       // 1024 threads, 2 elems each
    s[t]        = g_deg[t];
    s[t + 1024] = g_deg[t + 1024];
    __syncthreads();
    for (int d = 1; d < NN; d <<= 1) {
        int v0 = (t        >= d) ? s[t        - d] : 0;
        int v1 = (t + 1024 >= d) ? s[t + 1024 - d] : 0;
        __syncthreads();
        s[t]        += v0;
        s[t + 1024] += v1;
        __syncthreads();
    }
    g_off[t + 1]    = s[t];
    g_off[t + 1025] = s[t + 1024];
    if (t == 0) g_off[0] = 0;
    g_cur[t]        = (t == 0) ? 0 : s[t - 1];
    g_cur[t + 1024] = s[t + 1023];
}

__global__ void csr_fill_kernel(const void* edges, int E) {
    int e = blockIdx.x * blockDim.x + threadIdx.x;
    if (e >= E) return;
    int a, rel, b;
    load_edge(edges, e, a, rel, b);
    if (a < 0 || a >= NN || b < 0 || b >= NN) return;
    int flag = (rel > 0) ? 0x10000 : 0;
    int pa = atomicAdd(&g_cur[a], 1);
    g_adj[pa] = b | flag;                      // node a accumulates x[b]
    int pb = atomicAdd(&g_cur[b], 1);
    g_adj[pb] = a | flag;                      // node b accumulates x[a]
}

// ---------------------------------------------------------------------------
// Gather: block = (node n, feature half h). 256 threads, each owns 8 float4
// of the 8192-float half, accumulates over incident edges in registers.
// ---------------------------------------------------------------------------
__global__ void __launch_bounds__(256) gather_kernel(
        const float* __restrict__ x,
        float* __restrict__ neigh,
        float* __restrict__ nonneigh) {
    const int n = blockIdx.x;
    const int h = blockIdx.y;                  // 0 or 1
    const int t = threadIdx.x;

    float4 accN[8], accP[8];
#pragma unroll
    for (int j = 0; j < 8; j++) {
        accN[j] = make_float4(0.f, 0.f, 0.f, 0.f);
        accP[j] = make_float4(0.f, 0.f, 0.f, 0.f);
    }

    const int s = g_off[n], e = g_off[n + 1];
    const size_t base4h = (size_t)h * 2048;
    const float4* xb = (const float4*)x;

    for (int k = s; k < e; k++) {
        int ent = g_adj[k];
        int peer = ent & 0xFFFF;
        const float4* src = xb + (size_t)peer * (FEAT / 4) + base4h;
        if (ent & 0x10000) {
#pragma unroll
            for (int j = 0; j < 8; j++) {
                float4 v = src[t + 256 * j];
                accN[j].x += v.x; accN[j].y += v.y;
                accN[j].z += v.z; accN[j].w += v.w;
            }
        } else {
#pragma unroll
            for (int j = 0; j < 8; j++) {
                float4 v = src[t + 256 * j];
                accP[j].x += v.x; accP[j].y += v.y;
                accP[j].z += v.z; accP[j].w += v.w;
            }
        }
    }

    float4* dn = (float4*)neigh    + (size_t)n * (FEAT / 4) + base4h;
    float4* dp = (float4*)nonneigh + (size_t)n * (FEAT / 4) + base4h;
#pragma unroll
    for (int j = 0; j < 8; j++) {
        dn[t + 256 * j] = accN[j];
        dp[t + 256 * j] = accP[j];
    }
}

// ---------------------------------------------------------------------------
// Direct 3x3 conv, pad=1, NCHW, packed f32x2 (2 vertically adjacent output
// pixels per thread live in one 64-bit register; one FFMA2 = 2 MACs).
// Block = 256 threads = 32 (x) * 8 (row-pairs) -> 16 rows per block.
// Grid = (N, 2 row tiles). Input channels in chunks of 8; sources are up to
// 3 arrays of 16 channels each; chunk ch reads source ch>>1, offset (ch&1)*8.
// Weights staged in smem pre-duplicated as (w,w) 64-bit pairs, 9 taps padded
// to 10 so each [cl][co] row is 80 B (float4-pattern LDS, broadcast reads).
// ---------------------------------------------------------------------------
template <int CIN, int COUT>
__global__ void __launch_bounds__(256)
conv3x3_kernel(const float* __restrict__ src0,
               const float* __restrict__ src1,
               const float* __restrict__ src2,
               int imgStride,
               const float* __restrict__ w,
               const float* __restrict__ bias,
               float* __restrict__ out) {
    constexpr int NCH = CIN / 8;
    __shared__ float s_in[8 * 18 * 34];                  // 19.1 KB
    __shared__ unsigned long long s_w[8 * COUT * 10];    // <= 20 KB

    const int n     = blockIdx.x;
    const int rbase = blockIdx.y * 16;
    const int tx    = threadIdx.x & 31;
    const int ty    = threadIdx.x >> 5;        // 0..7 -> rows 2ty, 2ty+1

    unsigned long long acc[COUT];
#pragma unroll
    for (int co = 0; co < COUT; co++) {
        float bv = bias[co];
        acc[co] = pack2(bv, bv);
    }

#pragma unroll 1
    for (int ch = 0; ch < NCH; ch++) {
        const float* srcp = (ch >> 1) == 0 ? src0 : ((ch >> 1) == 1 ? src1 : src2);
        const float* base = srcp + (size_t)n * imgStride + (ch & 1) * 8 * HW;

        // stage input: 8 ch x 18 rows x 34 cols (zero-padded halo)
        for (int idx = threadIdx.x; idx < 8 * 18 * 34; idx += 256) {
            int c   = idx / 612;
            int rem = idx - c * 612;
            int r   = rem / 34;
            int col = rem - r * 34;
            int gr = rbase + r - 1;
            int gc = col - 1;
            float v = 0.f;
            if (gr >= 0 && gr < HH && gc >= 0 && gc < WW)
                v = base[c * HW + gr * WW + gc];
            s_in[idx] = v;
        }
        // stage weights duplicated: s_w[cl*COUT+co][tap] = (w,w)
        for (int idx = threadIdx.x; idx < 8 * COUT * 9; idx += 256) {
            int cl  = idx / (COUT * 9);
            int rr  = idx - cl * (COUT * 9);
            int co  = rr / 9;
            int tap = rr - co * 9;
            float wv = w[(size_t)(co * CIN + ch * 8 + cl) * 9 + tap];
            s_w[(cl * COUT + co) * 10 + tap] = pack2(wv, wv);
        }
        __syncthreads();

#pragma unroll 1
        for (int cl = 0; cl < 8; cl++) {
            // 4 rows x 3 cols of input covering both output pixels
            float iv[4][3];
#pragma unroll
            for (int rr = 0; rr < 4; rr++)
#pragma unroll
                for (int cc = 0; cc < 3; cc++)
                    iv[rr][cc] = s_in[(cl * 18 + 2 * ty + rr) * 34 + tx + cc];
            // 9 packed input pairs: p[ky*3+kx] = (iv[ky][kx], iv[ky+1][kx])
            unsigned long long p[9];
#pragma unroll
            for (int ky = 0; ky < 3; ky++)
#pragma unroll
                for (int kx = 0; kx < 3; kx++)
                    p[ky * 3 + kx] = pack2(iv[ky][kx], iv[ky + 1][kx]);

#pragma unroll
            for (int co = 0; co < COUT; co++) {
                const ulonglong2* wp = (const ulonglong2*)&s_w[(cl * COUT + co) * 10];
                ulonglong2 w01 = wp[0];
                ulonglong2 w23 = wp[1];
                ulonglong2 w45 = wp[2];
                ulonglong2 w67 = wp[3];
                unsigned long long w8 = s_w[(cl * COUT + co) * 10 + 8];
                unsigned long long a = acc[co];
                a = fma2(p[0], w01.x, a);
                a = fma2(p[1], w01.y, a);
                a = fma2(p[2], w23.x, a);
                a = fma2(p[3], w23.y, a);
                a = fma2(p[4], w45.x, a);
                a = fma2(p[5], w45.y, a);
                a = fma2(p[6], w67.x, a);
                a = fma2(p[7], w67.y, a);
                a = fma2(p[8], w8,    a);
                acc[co] = a;
            }
        }
        __syncthreads();
    }

    const int gr0 = rbase + 2 * ty;
    float* o = out + (size_t)n * COUT * HW + gr0 * WW + tx;
#pragma unroll
    for (int co = 0; co < COUT; co++) {
        float v0, v1;
        unpack2(acc[co], v0, v1);
        o[co * HW]      = v0;
        o[co * HW + WW] = v1;
    }
}

// ---------------------------------------------------------------------------
// Launch
// ---------------------------------------------------------------------------
extern "C" void kernel_launch(void* const* d_in, const int* in_sizes, int n_in,
                              void* d_out, int out_size) {
    const float* x     = (const float*)d_in[0];
    const void*  edges = (const void*)d_in[1];
    const float* w1    = (const float*)d_in[2];
    const float* b1    = (const float*)d_in[3];
    const float* w2    = (const float*)d_in[4];
    const float* b2    = (const float*)d_in[5];
    const float* w3    = (const float*)d_in[6];
    const float* b3    = (const float*)d_in[7];
    float*       out   = (float*)d_out;

    int E = in_sizes[1] / 3;
    if (E > EMAX) E = EMAX;

    float *neigh, *nonneigh, *h1, *h2;
    cudaGetSymbolAddress((void**)&neigh,    g_neigh);
    cudaGetSymbolAddress((void**)&nonneigh, g_nonneigh);
    cudaGetSymbolAddress((void**)&h1,       g_h1);
    cudaGetSymbolAddress((void**)&h2,       g_h2);

    probe_dtype_kernel<<<1, 1>>>(edges, E);

    // CSR build
    csr_zero_kernel<<<(NN + 255) / 256, 256>>>();
    csr_count_kernel<<<(E + 255) / 256, 256>>>(edges, E);
    csr_scan_kernel<<<1, 1024>>>();
    csr_fill_kernel<<<(E + 255) / 256, 256>>>(edges, E);

    // Message passing (gather, no atomics)
    dim3 ggrid(NN, 2);
    gather_kernel<<<ggrid, 256>>>(x, neigh, nonneigh);

    dim3 cgrid(NN, 2);
    // conv1: concat(x, neigh, nonneigh) [48ch] -> h1 [32ch]
    conv3x3_kernel<48, 32><<<cgrid, 256>>>(x, neigh, nonneigh, CC * HW,
                                           w1, b1, h1);
    // conv2: h1 [32ch] -> h2 [32ch]
    conv3x3_kernel<32, 32><<<cgrid, 256>>>(h1, h1 + 16 * HW, nullptr, 32 * HW,
                                           w2, b2, h2);
    // conv3: h2 [32ch] -> out [16ch]
    conv3x3_kernel<32, 16><<<cgrid, 256>>>(h2, h2 + 16 * HW, nullptr, 32 * HW,
                                           w3, b3, out);
}

// round 6
// speedup vs baseline: 1.1447x; 1.1447x over previous
#include <cuda_runtime.h>
#include <cuda_bf16.h>
#include <mma.h>
#include <cstdint>

using namespace nvcuda;

// ---------------------------------------------------------------------------
// Problem constants
// ---------------------------------------------------------------------------
#define NN    2048         // nodes / batch
#define CC    16           // channels of x
#define HH    32
#define WW    32
#define HW    (HH*WW)      // 1024
#define FEAT  (CC*HW)      // 16384 floats per node
#define EMAX  16384

// Scratch (device globals; no allocation allowed in kernel_launch)
__device__ float g_neigh   [NN * CC * HW];   // 134 MB
__device__ float g_nonneigh[NN * CC * HW];   // 134 MB
__device__ float g_h1      [NN * 32 * HW];   // 268 MB
__device__ float g_h2      [NN * 32 * HW];   // 268 MB
__device__ int   g_edges64;                  // 1 if edges buffer is int64
__device__ int   g_deg[NN];
__device__ int   g_off[NN + 1];
__device__ int   g_cur[NN];
__device__ int   g_adj[2 * EMAX];            // peer | (0x10000 if rel>0)

// ---------------------------------------------------------------------------
// Edge decode + probe (dtype decided at runtime)
// ---------------------------------------------------------------------------
__device__ __forceinline__ void load_edge(const void* edges, int e,
                                          int& a, int& rel, int& b) {
    if (g_edges64) {
        const long long* p = (const long long*)edges;
        a = (int)p[3 * e + 0]; rel = (int)p[3 * e + 1]; b = (int)p[3 * e + 2];
    } else {
        const int* p = (const int*)edges;
        a = p[3 * e + 0]; rel = p[3 * e + 1]; b = p[3 * e + 2];
    }
}

__global__ void probe_dtype_kernel(const void* edges, int E) {
    const long long* e64 = (const long long*)edges;
    bool ok = true;
    int n = E < 8 ? E : 8;
    for (int i = 0; i < n; i++) {
        long long a   = e64[3 * i + 0];
        long long rel = e64[3 * i + 1];
        long long b   = e64[3 * i + 2];
        if (a < 0 || a >= NN || b < 0 || b >= NN ||
            !(rel == 1 || rel == -1)) { ok = false; break; }
    }
    g_edges64 = ok ? 1 : 0;
}

// ---------------------------------------------------------------------------
// CSR build
// ---------------------------------------------------------------------------
__global__ void csr_zero_kernel() {
    int i = blockIdx.x * blockDim.x + threadIdx.x;
    if (i < NN) g_deg[i] = 0;
}

__global__ void csr_count_kernel(const void* edges, int E) {
    int e = blockIdx.x * blockDim.x + threadIdx.x;
    if (e >= E) return;
    int a, rel, b;
    load_edge(edges, e, a, rel, b);
    if (a < 0 || a >= NN || b < 0 || b >= NN) return;
    atomicAdd(&g_deg[a], 1);
    atomicAdd(&g_deg[b], 1);
}

__global__ void __launch_bounds__(1024) csr_scan_kernel() {
    __shared__ int s[NN];
    int t = threadIdx.x;
    s[t]        = g_deg[t];
    s[t + 1024] = g_deg[t + 1024];
    __syncthreads();
    for (int d = 1; d < NN; d <<= 1) {
        int v0 = (t        >= d) ? s[t        - d] : 0;
        int v1 = (t + 1024 >= d) ? s[t + 1024 - d] : 0;
        __syncthreads();
        s[t]        += v0;
        s[t + 1024] += v1;
        __syncthreads();
    }
    g_off[t + 1]    = s[t];
    g_off[t + 1025] = s[t + 1024];
    if (t == 0) g_off[0] = 0;
    g_cur[t]        = (t == 0) ? 0 : s[t - 1];
    g_cur[t + 1024] = s[t + 1023];
}

__global__ void csr_fill_kernel(const void* edges, int E) {
    int e = blockIdx.x * blockDim.x + threadIdx.x;
    if (e >= E) return;
    int a, rel, b;
    load_edge(edges, e, a, rel, b);
    if (a < 0 || a >= NN || b < 0 || b >= NN) return;
    int flag = (rel > 0) ? 0x10000 : 0;
    int pa = atomicAdd(&g_cur[a], 1);
    g_adj[pa] = b | flag;
    int pb = atomicAdd(&g_cur[b], 1);
    g_adj[pb] = a | flag;
}

// ---------------------------------------------------------------------------
// Gather: block = (node n, feature half h). No atomics.
// ---------------------------------------------------------------------------
__global__ void __launch_bounds__(256) gather_kernel(
        const float* __restrict__ x,
        float* __restrict__ neigh,
        float* __restrict__ nonneigh) {
    const int n = blockIdx.x;
    const int h = blockIdx.y;
    const int t = threadIdx.x;

    float4 accN[8], accP[8];
#pragma unroll
    for (int j = 0; j < 8; j++) {
        accN[j] = make_float4(0.f, 0.f, 0.f, 0.f);
        accP[j] = make_float4(0.f, 0.f, 0.f, 0.f);
    }

    const int s = g_off[n], e = g_off[n + 1];
    const size_t base4h = (size_t)h * 2048;
    const float4* xb = (const float4*)x;

    for (int k = s; k < e; k++) {
        int ent = g_adj[k];
        int peer = ent & 0xFFFF;
        const float4* src = xb + (size_t)peer * (FEAT / 4) + base4h;
        if (ent & 0x10000) {
#pragma unroll
            for (int j = 0; j < 8; j++) {
                float4 v = src[t + 256 * j];
                accN[j].x += v.x; accN[j].y += v.y;
                accN[j].z += v.z; accN[j].w += v.w;
            }
        } else {
#pragma unroll
            for (int j = 0; j < 8; j++) {
                float4 v = src[t + 256 * j];
                accP[j].x += v.x; accP[j].y += v.y;
                accP[j].z += v.z; accP[j].w += v.w;
            }
        }
    }

    float4* dn = (float4*)neigh    + (size_t)n * (FEAT / 4) + base4h;
    float4* dp = (float4*)nonneigh + (size_t)n * (FEAT / 4) + base4h;
#pragma unroll
    for (int j = 0; j < 8; j++) {
        dn[t + 256 * j] = accN[j];
        dp[t + 256 * j] = accP[j];
    }
}

// ---------------------------------------------------------------------------
// Conv 3x3 via wmma bf16 split-precision im2col GEMM (base-PTX HMMA path).
// Block = 256 threads = 8 warps, handles 256 pixels (8 image rows) of one
// node. Grid = (NN, 4). D[256 x COUT] = A_im2col[256 x K] * W[COUT x K]^T,
// K = 9*CIN tap-major, consumed in 32-wide chunks staged into smem.
// Split precision: v = hi + lo (bf16 each);
//   D = Ahi*Bhi + Alo*Bhi + Ahi*Blo  (error ~1.5e-5, fp32 accumulate).
// Accumulators initialized from a bias tile. Epilogue stores col-major
// (ldm = 1024) straight into NCHW output.
// ---------------------------------------------------------------------------
template <int CIN, int COUT, int KREAL, int NCHUNK>
__global__ void __launch_bounds__(256)
conv_wmma_kernel(const float* __restrict__ src0,
                 const float* __restrict__ src1,
                 const float* __restrict__ src2,
                 int imgStride,
                 const float* __restrict__ w,
                 const float* __restrict__ bias,
                 float* __restrict__ out) {
    constexpr int NT  = COUT / 16;             // n-tiles (2 or 1)
    constexpr int LDA = 36;                    // padded halves per A row
    __shared__ __nv_bfloat16 sA_hi[256 * LDA];
    __shared__ __nv_bfloat16 sA_lo[256 * LDA];
    __shared__ __nv_bfloat16 sB_hi[COUT * LDA];
    __shared__ __nv_bfloat16 sB_lo[COUT * LDA];
    __shared__ float sBias[16 * COUT];

    const int tid  = threadIdx.x;
    const int wid  = tid >> 5;
    const int n    = blockIdx.x;
    const int pix0 = blockIdx.y * 256;
    const int row0 = blockIdx.y * 8;

    // bias tile: 16 identical rows of bias[0..COUT)
    for (int idx = tid; idx < 16 * COUT; idx += 256)
        sBias[idx] = bias[idx & (COUT - 1)];
    __syncthreads();

    wmma::fragment<wmma::accumulator, 16, 16, 16, float> acc[2][NT];
#pragma unroll
    for (int m2 = 0; m2 < 2; m2++)
#pragma unroll
        for (int n2 = 0; n2 < NT; n2++)
            wmma::load_matrix_sync(acc[m2][n2], sBias + n2 * 16, COUT,
                                   wmma::mem_row_major);

    // per-thread pixel for A staging
    const int y = row0 + (tid >> 5);
    const int x = tid & 31;
    const float* p0 = src0 + (size_t)n * imgStride;
    const float* p1 = src1 ? src1 + (size_t)n * imgStride : p0;
    const float* p2 = src2 ? src2 + (size_t)n * imgStride : p0;

    union U4 { unsigned short s[4]; uint2 u; };

#pragma unroll 1
    for (int chunk = 0; chunk < NCHUNK; chunk++) {
        // ---- stage A: this thread's pixel row, 32 k-values, hi/lo ----
#pragma unroll
        for (int k0 = 0; k0 < 32; k0 += 4) {
            U4 uh, ul;
#pragma unroll
            for (int j = 0; j < 4; j++) {
                int kg = chunk * 32 + k0 + j;
                float v = 0.f;
                if (kg < KREAL) {
                    int tap = kg / CIN;
                    int cin = kg - tap * CIN;
                    int dy  = tap / 3;
                    int dx  = tap - dy * 3;
                    int yy = y + dy - 1;
                    int xx = x + dx - 1;
                    if ((unsigned)yy < HH && (unsigned)xx < WW) {
                        const float* sp = (cin < 16) ? p0
                                         : (cin < 32) ? p1 : p2;
                        v = sp[(cin & 15) * HW + yy * WW + xx];
                    }
                }
                __nv_bfloat16 bh = __float2bfloat16(v);
                __nv_bfloat16 bl = __float2bfloat16(v - __bfloat162float(bh));
                union { __nv_bfloat16 b; unsigned short u; } ch, cl;
                ch.b = bh; cl.b = bl;
                uh.s[j] = ch.u; ul.s[j] = cl.u;
            }
            *(uint2*)&sA_hi[tid * LDA + k0] = uh.u;
            *(uint2*)&sA_lo[tid * LDA + k0] = ul.u;
        }
        // ---- stage B: [co][k] hi/lo ----
        for (int idx = tid; idx < COUT * 32; idx += 256) {
            int co = idx >> 5;
            int k  = idx & 31;
            int kg = chunk * 32 + k;
            float v = 0.f;
            if (kg < KREAL) {
                int tap = kg / CIN;
                int cin = kg - tap * CIN;
                v = w[(size_t)(co * CIN + cin) * 9 + tap];
            }
            __nv_bfloat16 bh = __float2bfloat16(v);
            __nv_bfloat16 bl = __float2bfloat16(v - __bfloat162float(bh));
            sB_hi[co * LDA + k] = bh;
            sB_lo[co * LDA + k] = bl;
        }
        __syncthreads();

        // ---- compute: 2 k-steps of 16 ----
#pragma unroll
        for (int k2 = 0; k2 < 2; k2++) {
            wmma::fragment<wmma::matrix_b, 16, 16, 16, __nv_bfloat16,
                           wmma::col_major> b_hi[NT], b_lo[NT];
#pragma unroll
            for (int n2 = 0; n2 < NT; n2++) {
                wmma::load_matrix_sync(b_hi[n2],
                    &sB_hi[n2 * 16 * LDA + k2 * 16], LDA);
                wmma::load_matrix_sync(b_lo[n2],
                    &sB_lo[n2 * 16 * LDA + k2 * 16], LDA);
            }
#pragma unroll
            for (int m2 = 0; m2 < 2; m2++) {
                const int mrow = (wid * 2 + m2) * 16;
                wmma::fragment<wmma::matrix_a, 16, 16, 16, __nv_bfloat16,
                               wmma::row_major> a_hi, a_lo;
                wmma::load_matrix_sync(a_hi, &sA_hi[mrow * LDA + k2 * 16], LDA);
                wmma::load_matrix_sync(a_lo, &sA_lo[mrow * LDA + k2 * 16], LDA);
#pragma unroll
                for (int n2 = 0; n2 < NT; n2++) {
                    wmma::mma_sync(acc[m2][n2], a_hi, b_hi[n2], acc[m2][n2]);
                    wmma::mma_sync(acc[m2][n2], a_lo, b_hi[n2], acc[m2][n2]);
                    wmma::mma_sync(acc[m2][n2], a_hi, b_lo[n2], acc[m2][n2]);
                }
            }
        }
        __syncthreads();
    }

    // ---- epilogue: D element (m, co) -> out[co*1024 + pix0 + m] ----
    float* optr = out + (size_t)n * COUT * HW + pix0;
#pragma unroll
    for (int m2 = 0; m2 < 2; m2++)
#pragma unroll
        for (int n2 = 0; n2 < NT; n2++)
            wmma::store_matrix_sync(
                optr + n2 * 16 * HW + (wid * 2 + m2) * 16,
                acc[m2][n2], HW, wmma::mem_col_major);
}

// ---------------------------------------------------------------------------
// Launch
// ---------------------------------------------------------------------------
extern "C" void kernel_launch(void* const* d_in, const int* in_sizes, int n_in,
                              void* d_out, int out_size) {
    const float* x     = (const float*)d_in[0];
    const void*  edges = (const void*)d_in[1];
    const float* w1    = (const float*)d_in[2];
    const float* b1    = (const float*)d_in[3];
    const float* w2    = (const float*)d_in[4];
    const float* b2    = (const float*)d_in[5];
    const float* w3    = (const float*)d_in[6];
    const float* b3    = (const float*)d_in[7];
    float*       out   = (float*)d_out;

    int E = in_sizes[1] / 3;
    if (E > EMAX) E = EMAX;

    float *neigh, *nonneigh, *h1, *h2;
    cudaGetSymbolAddress((void**)&neigh,    g_neigh);
    cudaGetSymbolAddress((void**)&nonneigh, g_nonneigh);
    cudaGetSymbolAddress((void**)&h1,       g_h1);
    cudaGetSymbolAddress((void**)&h2,       g_h2);

    probe_dtype_kernel<<<1, 1>>>(edges, E);

    csr_zero_kernel<<<(NN + 255) / 256, 256>>>();
    csr_count_kernel<<<(E + 255) / 256, 256>>>(edges, E);
    csr_scan_kernel<<<1, 1024>>>();
    csr_fill_kernel<<<(E + 255) / 256, 256>>>(edges, E);

    dim3 ggrid(NN, 2);
    gather_kernel<<<ggrid, 256>>>(x, neigh, nonneigh);

    dim3 cgrid(NN, 4);
    // conv1: concat(x, neigh, nonneigh) [48ch] -> h1 [32ch], K=432 (14 chunks)
    conv_wmma_kernel<48, 32, 432, 14><<<cgrid, 256>>>(
        x, neigh, nonneigh, CC * HW, w1, b1, h1);
    // conv2: h1 [32ch] -> h2 [32ch], K=288 (9 chunks)
    conv_wmma_kernel<32, 32, 288, 9><<<cgrid, 256>>>(
        h1, h1 + 16 * HW, nullptr, 32 * HW, w2, b2, h2);
    // conv3: h2 [32ch] -> out [16ch], K=288 (9 chunks)
    conv_wmma_kernel<32, 16, 288, 9><<<cgrid, 256>>>(
        h2, h2 + 16 * HW, nullptr, 32 * HW, w3, b3, out);
}

// round 7
// speedup vs baseline: 2.3067x; 2.0151x over previous
#include <cuda_runtime.h>
#include <cuda_bf16.h>
#include <mma.h>
#include <cstdint>

using namespace nvcuda;

// ---------------------------------------------------------------------------
// Problem constants
// ---------------------------------------------------------------------------
#define NN    2048         // nodes / batch
#define CC    16           // channels of x
#define HH    32
#define WW    32
#define HW    (HH*WW)      // 1024
#define FEAT  (CC*HW)      // 16384 floats per node
#define EMAX  16384

// Scratch (device globals; no allocation allowed in kernel_launch)
__device__ float g_neigh   [NN * CC * HW];   // 134 MB
__device__ float g_nonneigh[NN * CC * HW];   // 134 MB
__device__ float g_h1      [NN * 32 * HW];   // 268 MB
__device__ float g_h2      [NN * 32 * HW];   // 268 MB
__device__ int   g_edges64;
__device__ int   g_deg[NN];
__device__ int   g_off[NN + 1];
__device__ int   g_cur[NN];
__device__ int   g_adj[2 * EMAX];            // peer | (0x10000 if rel>0)

// Pre-split weights (bf16 hi/lo), K-ordered: k = (tap*(CIN/16)+cc)*16 + j,
// cin = cc*16+j. Row stride LDB (440 / 296) for conflict-free fragment loads.
__device__ __align__(16) __nv_bfloat16 g_b1hi[32 * 440];
__device__ __align__(16) __nv_bfloat16 g_b1lo[32 * 440];
__device__ __align__(16) __nv_bfloat16 g_b2hi[32 * 296];
__device__ __align__(16) __nv_bfloat16 g_b2lo[32 * 296];
__device__ __align__(16) __nv_bfloat16 g_b3hi[16 * 296];
__device__ __align__(16) __nv_bfloat16 g_b3lo[16 * 296];

// ---------------------------------------------------------------------------
// Edge decode + probe (dtype decided at runtime)
// ---------------------------------------------------------------------------
__device__ __forceinline__ void load_edge(const void* edges, int e,
                                          int& a, int& rel, int& b) {
    if (g_edges64) {
        const long long* p = (const long long*)edges;
        a = (int)p[3 * e + 0]; rel = (int)p[3 * e + 1]; b = (int)p[3 * e + 2];
    } else {
        const int* p = (const int*)edges;
        a = p[3 * e + 0]; rel = p[3 * e + 1]; b = p[3 * e + 2];
    }
}

__global__ void probe_dtype_kernel(const void* edges, int E) {
    const long long* e64 = (const long long*)edges;
    bool ok = true;
    int n = E < 8 ? E : 8;
    for (int i = 0; i < n; i++) {
        long long a   = e64[3 * i + 0];
        long long rel = e64[3 * i + 1];
        long long b   = e64[3 * i + 2];
        if (a < 0 || a >= NN || b < 0 || b >= NN ||
            !(rel == 1 || rel == -1)) { ok = false; break; }
    }
    g_edges64 = ok ? 1 : 0;
}

// ---------------------------------------------------------------------------
// CSR build
// ---------------------------------------------------------------------------
__global__ void csr_zero_kernel() {
    int i = blockIdx.x * blockDim.x + threadIdx.x;
    if (i < NN) g_deg[i] = 0;
}

__global__ void csr_count_kernel(const void* edges, int E) {
    int e = blockIdx.x * blockDim.x + threadIdx.x;
    if (e >= E) return;
    int a, rel, b;
    load_edge(edges, e, a, rel, b);
    if (a < 0 || a >= NN || b < 0 || b >= NN) return;
    atomicAdd(&g_deg[a], 1);
    atomicAdd(&g_deg[b], 1);
}

__global__ void __launch_bounds__(1024) csr_scan_kernel() {
    __shared__ int s[NN];
    int t = threadIdx.x;
    s[t]        = g_deg[t];
    s[t + 1024] = g_deg[t + 1024];
    __syncthreads();
    for (int d = 1; d < NN; d <<= 1) {
        int v0 = (t        >= d) ? s[t        - d] : 0;
        int v1 = (t + 1024 >= d) ? s[t + 1024 - d] : 0;
        __syncthreads();
        s[t]        += v0;
        s[t + 1024] += v1;
        __syncthreads();
    }
    g_off[t + 1]    = s[t];
    g_off[t + 1025] = s[t + 1024];
    if (t == 0) g_off[0] = 0;
    g_cur[t]        = (t == 0) ? 0 : s[t - 1];
    g_cur[t + 1024] = s[t + 1023];
}

__global__ void csr_fill_kernel(const void* edges, int E) {
    int e = blockIdx.x * blockDim.x + threadIdx.x;
    if (e >= E) return;
    int a, rel, b;
    load_edge(edges, e, a, rel, b);
    if (a < 0 || a >= NN || b < 0 || b >= NN) return;
    int flag = (rel > 0) ? 0x10000 : 0;
    int pa = atomicAdd(&g_cur[a], 1);
    g_adj[pa] = b | flag;
    int pb = atomicAdd(&g_cur[b], 1);
    g_adj[pb] = a | flag;
}

// ---------------------------------------------------------------------------
// Gather: block = (node n, feature half h). No atomics.
// ---------------------------------------------------------------------------
__global__ void __launch_bounds__(256) gather_kernel(
        const float* __restrict__ x,
        float* __restrict__ neigh,
        float* __restrict__ nonneigh) {
    const int n = blockIdx.x;
    const int h = blockIdx.y;
    const int t = threadIdx.x;

    float4 accN[8], accP[8];
#pragma unroll
    for (int j = 0; j < 8; j++) {
        accN[j] = make_float4(0.f, 0.f, 0.f, 0.f);
        accP[j] = make_float4(0.f, 0.f, 0.f, 0.f);
    }

    const int s = g_off[n], e = g_off[n + 1];
    const size_t base4h = (size_t)h * 2048;
    const float4* xb = (const float4*)x;

    for (int k = s; k < e; k++) {
        int ent = g_adj[k];
        int peer = ent & 0xFFFF;
        const float4* src = xb + (size_t)peer * (FEAT / 4) + base4h;
        if (ent & 0x10000) {
#pragma unroll
            for (int j = 0; j < 8; j++) {
                float4 v = src[t + 256 * j];
                accN[j].x += v.x; accN[j].y += v.y;
                accN[j].z += v.z; accN[j].w += v.w;
            }
        } else {
#pragma unroll
            for (int j = 0; j < 8; j++) {
                float4 v = src[t + 256 * j];
                accP[j].x += v.x; accP[j].y += v.y;
                accP[j].z += v.z; accP[j].w += v.w;
            }
        }
    }

    float4* dn = (float4*)neigh    + (size_t)n * (FEAT / 4) + base4h;
    float4* dp = (float4*)nonneigh + (size_t)n * (FEAT / 4) + base4h;
#pragma unroll
    for (int j = 0; j < 8; j++) {
        dn[t + 256 * j] = accN[j];
        dp[t + 256 * j] = accP[j];
    }
}

// ---------------------------------------------------------------------------
// Weight split prep: fp32 -> bf16 hi/lo, K-ordered rows of length LDB.
// ---------------------------------------------------------------------------
__global__ void prep_b_kernel(const float* __restrict__ w1,
                              const float* __restrict__ w2,
                              const float* __restrict__ w3) {
    int idx = blockIdx.x * blockDim.x + threadIdx.x;
    // conv1: 32 co x 432 k  (CIN=48, NCC=3)
    if (idx < 32 * 432) {
        int co = idx / 432, k = idx - co * 432;
        int ks = k >> 4, j = k & 15;
        int tap = ks / 3, cc = ks - tap * 3;
        float v = w1[(size_t)(co * 48 + cc * 16 + j) * 9 + tap];
        __nv_bfloat16 bh = __float2bfloat16(v);
        g_b1hi[co * 440 + k] = bh;
        g_b1lo[co * 440 + k] = __float2bfloat16(v - __bfloat162float(bh));
    }
    // conv2: 32 co x 288 k (CIN=32, NCC=2)
    if (idx < 32 * 288) {
        int co = idx / 288, k = idx - co * 288;
        int ks = k >> 4, j = k & 15;
        int tap = ks >> 1, cc = ks & 1;
        float v = w2[(size_t)(co * 32 + cc * 16 + j) * 9 + tap];
        __nv_bfloat16 bh = __float2bfloat16(v);
        g_b2hi[co * 296 + k] = bh;
        g_b2lo[co * 296 + k] = __float2bfloat16(v - __bfloat162float(bh));
    }
    // conv3: 16 co x 288 k
    if (idx < 16 * 288) {
        int co = idx / 288, k = idx - co * 288;
        int ks = k >> 4, j = k & 15;
        int tap = ks >> 1, cc = ks & 1;
        float v = w3[(size_t)(co * 32 + cc * 16 + j) * 9 + tap];
        __nv_bfloat16 bh = __float2bfloat16(v);
        g_b3hi[co * 296 + k] = bh;
        g_b3lo[co * 296 + k] = __float2bfloat16(v - __bfloat162float(bh));
    }
}

// ---------------------------------------------------------------------------
// Conv 3x3 as 9 shifted GEMMs (wmma bf16, split precision, fp32 accum).
// Block: 256 thr = 8 warps, ROWS output rows (ROWS*32 pixels) of one node.
// A tile staged ONCE to smem as [pixel(34-wide, halo)][cin padded CINPAD],
// bf16 hi/lo. A-fragment for tap (dy,dx) = pointer offset, no copies.
// K-step ks = tap*(CIN/16)+cc. D = Ahi*Bhi + Alo*Bhi + Ahi*Blo.
// ---------------------------------------------------------------------------
template <int CIN, int CINPAD, int COUT, int ROWS, int LDB, int KSTEPS>
__global__ void __launch_bounds__(256)
conv_shift_kernel(const float* __restrict__ src0,
                  const float* __restrict__ src1,
                  const float* __restrict__ src2,
                  int imgStride,
                  const __nv_bfloat16* __restrict__ Bhi,
                  const __nv_bfloat16* __restrict__ Blo,
                  const float* __restrict__ bias,
                  float* __restrict__ out) {
    extern __shared__ __align__(16) char smem[];
    constexpr int TIN = (ROWS + 2) * 34;       // tile pixels (with halo)
    constexpr int ASZ = TIN * CINPAD;          // elements per A half
    constexpr int BSZ = COUT * LDB;
    constexpr int NT  = COUT / 16;
    constexpr int MT  = ROWS / 4;              // m-tiles per warp
    constexpr int NCC = CIN / 16;

    __nv_bfloat16* sA_hi = (__nv_bfloat16*)smem;
    __nv_bfloat16* sA_lo = sA_hi + ASZ;
    __nv_bfloat16* sB_hi = sA_lo + ASZ;
    __nv_bfloat16* sB_lo = sB_hi + BSZ;
    float*         sBias = (float*)(sB_lo + BSZ);

    const int tid  = threadIdx.x;
    const int wid  = tid >> 5;
    const int n    = blockIdx.x;
    const int row0 = blockIdx.y * ROWS;
    const int pix0 = row0 * 32;

    // ---- B copy (global bf16 -> smem), uint4 ----
    {
        const uint4* g1 = (const uint4*)Bhi;
        const uint4* g2 = (const uint4*)Blo;
        uint4* s1 = (uint4*)sB_hi;
        uint4* s2 = (uint4*)sB_lo;
        constexpr int NB = BSZ * 2 / 16;
        for (int i = tid; i < NB; i += 256) { s1[i] = g1[i]; s2[i] = g2[i]; }
    }
    // ---- bias tile (16 rows, all = bias) ----
    for (int i = tid; i < 16 * COUT; i += 256) sBias[i] = bias[i & (COUT - 1)];

    // ---- A staging: fp32 -> bf16 hi/lo, transposed [pixel][cin] ----
    const float* p0 = src0 + (size_t)n * imgStride;
    const float* p1 = src1 ? src1 + (size_t)n * imgStride : p0;
    const float* p2 = src2 ? src2 + (size_t)n * imgStride : p0;
    for (int idx = tid; idx < CIN * TIN; idx += 256) {
        int cin = idx / TIN;
        int pix = idx - cin * TIN;
        int r = pix / 34, c = pix - r * 34;
        int y = row0 + r - 1, x = c - 1;
        float v = 0.f;
        if ((unsigned)y < HH && (unsigned)x < WW) {
            const float* sp = (cin < 16) ? p0 : (cin < 32) ? p1 : p2;
            v = sp[(cin & 15) * HW + y * WW + x];
        }
        __nv_bfloat16 bh = __float2bfloat16(v);
        sA_hi[pix * CINPAD + cin] = bh;
        sA_lo[pix * CINPAD + cin] = __float2bfloat16(v - __bfloat162float(bh));
    }
    __syncthreads();

    wmma::fragment<wmma::accumulator, 16, 16, 16, float> acc[MT][NT];
#pragma unroll
    for (int m2 = 0; m2 < MT; m2++)
#pragma unroll
        for (int n2 = 0; n2 < NT; n2++)
            wmma::load_matrix_sync(acc[m2][n2], sBias + n2 * 16, COUT,
                                   wmma::mem_row_major);

#pragma unroll 1
    for (int ks = 0; ks < KSTEPS; ks++) {
        const int tap = ks / NCC;
        const int cc  = ks - tap * NCC;
        const int dy  = tap / 3;
        const int dx  = tap - dy * 3;

        wmma::fragment<wmma::matrix_b, 16, 16, 16, __nv_bfloat16,
                       wmma::col_major> b_hi[NT], b_lo[NT];
#pragma unroll
        for (int n2 = 0; n2 < NT; n2++) {
            wmma::load_matrix_sync(b_hi[n2], &sB_hi[n2 * 16 * LDB + ks * 16], LDB);
            wmma::load_matrix_sync(b_lo[n2], &sB_lo[n2 * 16 * LDB + ks * 16], LDB);
        }
#pragma unroll
        for (int m2 = 0; m2 < MT; m2++) {
            const int mt   = wid * MT + m2;
            const int yloc = mt >> 1;
            const int x0   = (mt & 1) * 16;
            const int ab   = ((yloc + dy) * 34 + x0 + dx) * CINPAD + cc * 16;
            wmma::fragment<wmma::matrix_a, 16, 16, 16, __nv_bfloat16,
                           wmma::row_major> a_hi, a_lo;
            wmma::load_matrix_sync(a_hi, &sA_hi[ab], CINPAD);
            wmma::load_matrix_sync(a_lo, &sA_lo[ab], CINPAD);
#pragma unroll
            for (int n2 = 0; n2 < NT; n2++) {
                wmma::mma_sync(acc[m2][n2], a_hi, b_hi[n2], acc[m2][n2]);
                wmma::mma_sync(acc[m2][n2], a_lo, b_hi[n2], acc[m2][n2]);
                wmma::mma_sync(acc[m2][n2], a_hi, b_lo[n2], acc[m2][n2]);
            }
        }
    }

    // ---- epilogue: element (m, co) -> out[co*HW + pix0 + m] ----
    float* optr = out + (size_t)n * COUT * HW + pix0;
#pragma unroll
    for (int m2 = 0; m2 < MT; m2++)
#pragma unroll
        for (int n2 = 0; n2 < NT; n2++)
            wmma::store_matrix_sync(
                optr + n2 * 16 * HW + (wid * MT + m2) * 16,
                acc[m2][n2], HW, wmma::mem_col_major);
}

// ---------------------------------------------------------------------------
// Launch
// ---------------------------------------------------------------------------
extern "C" void kernel_launch(void* const* d_in, const int* in_sizes, int n_in,
                              void* d_out, int out_size) {
    const float* x     = (const float*)d_in[0];
    const void*  edges = (const void*)d_in[1];
    const float* w1    = (const float*)d_in[2];
    const float* b1    = (const float*)d_in[3];
    const float* w2    = (const float*)d_in[4];
    const float* b2    = (const float*)d_in[5];
    const float* w3    = (const float*)d_in[6];
    const float* b3    = (const float*)d_in[7];
    float*       out   = (float*)d_out;

    int E = in_sizes[1] / 3;
    if (E > EMAX) E = EMAX;

    float *neigh, *nonneigh, *h1, *h2;
    cudaGetSymbolAddress((void**)&neigh,    g_neigh);
    cudaGetSymbolAddress((void**)&nonneigh, g_nonneigh);
    cudaGetSymbolAddress((void**)&h1,       g_h1);
    cudaGetSymbolAddress((void**)&h2,       g_h2);
    __nv_bfloat16 *b1h, *b1l, *b2h, *b2l, *b3h, *b3l;
    cudaGetSymbolAddress((void**)&b1h, g_b1hi);
    cudaGetSymbolAddress((void**)&b1l, g_b1lo);
    cudaGetSymbolAddress((void**)&b2h, g_b2hi);
    cudaGetSymbolAddress((void**)&b2l, g_b2lo);
    cudaGetSymbolAddress((void**)&b3h, g_b3hi);
    cudaGetSymbolAddress((void**)&b3l, g_b3lo);

    probe_dtype_kernel<<<1, 1>>>(edges, E);

    csr_zero_kernel<<<(NN + 255) / 256, 256>>>();
    csr_count_kernel<<<(E + 255) / 256, 256>>>(edges, E);
    csr_scan_kernel<<<1, 1024>>>();
    csr_fill_kernel<<<(E + 255) / 256, 256>>>(edges, E);

    dim3 ggrid(NN, 2);
    gather_kernel<<<ggrid, 256>>>(x, neigh, nonneigh);

    prep_b_kernel<<<(32 * 432 + 255) / 256, 256>>>(w1, w2, w3);

    // smem: 2*ASZ*2B + 2*BSZ*2B + 16*COUT*4B
    const int smem1 = 2 * (6 * 34 * 56) * 2 + 2 * (32 * 440) * 2 + 2048;  // 104064
    const int smem2 = 2 * (10 * 34 * 40) * 2 + 2 * (32 * 296) * 2 + 2048; //  94336
    const int smem3 = 2 * (10 * 34 * 40) * 2 + 2 * (16 * 296) * 2 + 1024; //  74368

    static bool attr_set = false;
    if (!attr_set) {
        cudaFuncSetAttribute((const void*)conv_shift_kernel<48, 56, 32, 4, 440, 27>,
                             cudaFuncAttributeMaxDynamicSharedMemorySize, smem1);
        cudaFuncSetAttribute((const void*)conv_shift_kernel<32, 40, 32, 8, 296, 18>,
                             cudaFuncAttributeMaxDynamicSharedMemorySize, smem2);
        cudaFuncSetAttribute((const void*)conv_shift_kernel<32, 40, 16, 8, 296, 18>,
                             cudaFuncAttributeMaxDynamicSharedMemorySize, smem3);
        attr_set = true;
    }

    // conv1: concat(x, neigh, nonneigh) [48] -> h1 [32]; 4 rows/block
    conv_shift_kernel<48, 56, 32, 4, 440, 27><<<dim3(NN, 8), 256, smem1>>>(
        x, neigh, nonneigh, CC * HW, b1h, b1l, b1, h1);
    // conv2: h1 [32] -> h2 [32]; 8 rows/block
    conv_shift_kernel<32, 40, 32, 8, 296, 18><<<dim3(NN, 4), 256, smem2>>>(
        h1, h1 + 16 * HW, nullptr, 32 * HW, b2h, b2l, b2, h2);
    // conv3: h2 [32] -> out [16]; 8 rows/block
    conv_shift_kernel<32, 40, 16, 8, 296, 18><<<dim3(NN, 4), 256, smem3>>>(
        h2, h2 + 16 * HW, nullptr, 32 * HW, b3h, b3l, b3, out);
}